// round 2
// baseline (speedup 1.0000x reference)
#include <cuda_runtime.h>
#include <stdint.h>
#include <math.h>

// Problem constants
#define Tn    2048
#define EMB   128
#define NH    8
#define Mv    9      // M
#define Pp    36     // P
#define BT    4096   // B*T
#define D1    1024   // NH*EMB
#define D3    3072   // 3*D1

// Scratch (static device arrays; no allocation allowed)
__device__ float g_qkv[BT * D3];      // rows: [Q(1024) | K(1024) | V(1024)]
__device__ float g_attnout[BT * D1];
__device__ int   g_idx[BT * Pp];
__device__ float g_w[BT * Pp];

// ---------------- threefry-2x32 (JAX-compatible, 20 rounds) ----------------
__device__ __forceinline__ void tf2x32(uint32_t k0, uint32_t k1,
                                       uint32_t& x0, uint32_t& x1) {
  uint32_t ks2 = k0 ^ k1 ^ 0x1BD11BDAu;
  x0 += k0; x1 += k1;
#define TFR(r) { x0 += x1; x1 = (x1 << (r)) | (x1 >> (32 - (r))); x1 ^= x0; }
  TFR(13) TFR(15) TFR(26) TFR(6)
  x0 += k1;  x1 += ks2 + 1u;
  TFR(17) TFR(29) TFR(16) TFR(24)
  x0 += ks2; x1 += k0 + 2u;
  TFR(13) TFR(15) TFR(26) TFR(6)
  x0 += k0;  x1 += k1 + 3u;
  TFR(17) TFR(29) TFR(16) TFR(24)
  x0 += k1;  x1 += ks2 + 4u;
  TFR(13) TFR(15) TFR(26) TFR(6)
  x0 += ks2; x1 += k0 + 5u;
#undef TFR
}

// ---------------- Kernel 1: fused QKV projection GEMM ----------------------
// C(4096 x 3072) = X(4096 x 128) @ [Wq | Wk | Wv], Q/K scaled by 1/128^0.25
__global__ __launch_bounds__(256) void qkv_gemm(const float* __restrict__ X,
                                                const float* __restrict__ Wq,
                                                const float* __restrict__ Wk,
                                                const float* __restrict__ Wv) {
  __shared__ float As[64][68];   // [m][k] padded
  __shared__ float Bs[64][64];   // [k][n]
  int bm = blockIdx.y, bn = blockIdx.x;
  int cstart = bn * 64;
  int seg = cstart >> 10;
  const float* W = (seg == 0) ? Wq : ((seg == 1) ? Wk : Wv);
  int ccol = cstart & 1023;
  float scale = (seg < 2) ? 0.29730177875068026f : 1.0f; // 1/128^0.25
  int tid = threadIdx.x;
  int ty = tid >> 4, tx = tid & 15;
  float acc[4][4] = {};
  for (int kc = 0; kc < 128; kc += 64) {
    // load X tile 64x64 (rows bm*64.., cols kc..)
#pragma unroll
    for (int it = 0; it < 4; it++) {
      int lin = tid + it * 256;      // float4 index 0..1023
      int r = lin >> 4, c4 = lin & 15;
      float4 v = *(const float4*)(X + (size_t)(bm * 64 + r) * 128 + kc + c4 * 4);
      *(float4*)&As[r][c4 * 4] = v;
    }
    // load W tile 64x64 (rows kc.., cols ccol..)
#pragma unroll
    for (int it = 0; it < 4; it++) {
      int lin = tid + it * 256;
      int k = lin >> 4, c4 = lin & 15;
      float4 v = *(const float4*)(W + (size_t)(kc + k) * 1024 + ccol + c4 * 4);
      *(float4*)&Bs[k][c4 * 4] = v;
    }
    __syncthreads();
#pragma unroll 8
    for (int k = 0; k < 64; k++) {
      float a0 = As[ty * 4 + 0][k], a1 = As[ty * 4 + 1][k];
      float a2 = As[ty * 4 + 2][k], a3 = As[ty * 4 + 3][k];
      float4 b = *(const float4*)&Bs[k][tx * 4];
      acc[0][0] += a0 * b.x; acc[0][1] += a0 * b.y; acc[0][2] += a0 * b.z; acc[0][3] += a0 * b.w;
      acc[1][0] += a1 * b.x; acc[1][1] += a1 * b.y; acc[1][2] += a1 * b.z; acc[1][3] += a1 * b.w;
      acc[2][0] += a2 * b.x; acc[2][1] += a2 * b.y; acc[2][2] += a2 * b.z; acc[2][3] += a2 * b.w;
      acc[3][0] += a3 * b.x; acc[3][1] += a3 * b.y; acc[3][2] += a3 * b.z; acc[3][3] += a3 * b.w;
    }
    __syncthreads();
  }
#pragma unroll
  for (int i = 0; i < 4; i++) {
    float4 o = make_float4(acc[i][0] * scale, acc[i][1] * scale,
                           acc[i][2] * scale, acc[i][3] * scale);
    *(float4*)(g_qkv + (size_t)(bm * 64 + ty * 4 + i) * D3 + cstart + tx * 4) = o;
  }
}

// ---------------- Kernel 2: indices + weights per token --------------------
__global__ __launch_bounds__(64) void idxw_kernel(const float* __restrict__ sp,
                                                  const float* __restrict__ mvals) {
  int token = blockIdx.x;            // 0..4095
  int b = token >> 11, t = token & 2047;
  int p = threadIdx.x;
  __shared__ float s_mean[Mv];
  __shared__ float s_sigma_inv;
  __shared__ int   s_idx[Pp];
  __shared__ float s_ptsfl[Pp];
  __shared__ float s_dens[Pp][Mv];
  __shared__ float s_colinv[Mv];

  float dil = sp[0];
  if (p < Mv) {
    // exact mul+add (no FMA contraction) to match JAX rounding
    float off = __fmul_rn((float)(p - 4), dil);
    float mu  = __fadd_rn((float)t, off);
    mu = fminf(fmaxf(mu, 0.0f), (float)(Tn - 1));
    s_mean[p] = mu;
  }
  if (p == 0) {
    float s = sp[1] + 2.0f;                 // SIGMA_BOOST
    float sigma = log1pf(expf(s)) + 1e-7f;  // softplus + EPS
    s_sigma_inv = 1.0f / sigma;
  }
  __syncthreads();

  if (p < Pp) {
    int m = p >> 2, slot = p & 3;
    float fl = floorf(s_mean[m]);
    float val;
    if (slot == 0) val = fl;
    else if (slot == 1) val = fl + 1.0f;
    else {
      // JAX partitionable threefry (default since jax 0.4.36+):
      //   split(key(42))[1] = threefry2x32((0,42), (0, 1))  [both words]
      //   random_bits elem i = b1 ^ b2 where (b1,b2)=threefry2x32(k2, (0, i))
      //   randint span 2048 (pow2, multiplier=0) -> lower_bits & 2047
      uint32_t k2a = 0u, k2b = 1u;
      tf2x32(0u, 42u, k2a, k2b);          // second split key (both output words)
      uint32_t i = (uint32_t)(b * 36864 + t * 18 + m * 2 + (slot - 2));
      uint32_t x0 = 0u, x1 = i;           // hi32 / lo32 of 64-bit flat index
      tf2x32(k2a, k2b, x0, x1);
      uint32_t bits = x0 ^ x1;            // xor-fold for 32-bit bit_width
      val = (float)(bits & 2047u);
    }
    val = fminf(fmaxf(val, 0.0f), (float)(Tn - 1));
    int iv = (int)val;
    s_idx[p] = iv;
    s_ptsfl[p] = (float)iv;
  }
  __syncthreads();

  if (p < Pp) {
    bool dup = false;
    int my = s_idx[p];
    for (int q = 0; q < p; q++) dup |= (s_idx[q] == my);
    float inv_s = s_sigma_inv;
#pragma unroll
    for (int m = 0; m < Mv; m++) {
      float d = (s_ptsfl[p] - s_mean[m]) * inv_s;
      s_dens[p][m] = dup ? 0.0f : expf(-0.5f * d * d);
    }
  }
  __syncthreads();

  if (p < Mv) {
    float sum = 0.0f;
    for (int q = 0; q < Pp; q++) sum += s_dens[q][p];
    s_colinv[p] = 1.0f / sum;
  }
  __syncthreads();

  if (p < Pp) {
    float w = 0.0f;
#pragma unroll
    for (int m = 0; m < Mv; m++) w += s_dens[p][m] * s_colinv[m] * mvals[m];
    g_idx[token * Pp + p] = s_idx[p];
    g_w[token * Pp + p] = w;
  }
}

// ---------------- Kernel 3: gathered attention (1 warp per (b,h,t)) --------
__global__ __launch_bounds__(128) void attn_kernel() {
  int gw = (blockIdx.x * blockDim.x + threadIdx.x) >> 5;
  int lane = threadIdx.x & 31;
  int wslot = (threadIdx.x >> 5);
  __shared__ float s_logit[4][Pp];
  if (gw >= BT * NH) return;
  int h = gw & 7;
  int token = gw >> 3;
  int b = token >> 11;

  float4 q = *(const float4*)(g_qkv + (size_t)token * D3 + h * EMB + lane * 4);

  const int* ip = g_idx + token * Pp;
  const float* wp = g_w + token * Pp;
  int   idxA = ip[lane];
  float wA   = wp[lane];
  int   idxB = (lane < 4) ? ip[32 + lane] : 0;
  float wB   = (lane < 4) ? wp[32 + lane] : 0.0f;

  size_t rowbase = (size_t)(b * Tn) * D3;

  for (int p = 0; p < Pp; p++) {
    int   j = (p < 32) ? __shfl_sync(0xffffffffu, idxA, p)
                       : __shfl_sync(0xffffffffu, idxB, p - 32);
    float w = (p < 32) ? __shfl_sync(0xffffffffu, wA, p)
                       : __shfl_sync(0xffffffffu, wB, p - 32);
    float4 k4 = *(const float4*)(g_qkv + rowbase + (size_t)j * D3 + D1 + h * EMB + lane * 4);
    float d = q.x * k4.x + q.y * k4.y + q.z * k4.z + q.w * k4.w;
    d += __shfl_xor_sync(0xffffffffu, d, 16);
    d += __shfl_xor_sync(0xffffffffu, d, 8);
    d += __shfl_xor_sync(0xffffffffu, d, 4);
    d += __shfl_xor_sync(0xffffffffu, d, 2);
    d += __shfl_xor_sync(0xffffffffu, d, 1);
    if (lane == 0) s_logit[wslot][p] = w * d;
  }
  __syncwarp();

  float mx = -1e30f;
#pragma unroll
  for (int p = 0; p < Pp; p++) mx = fmaxf(mx, s_logit[wslot][p]);

  float4 acc = make_float4(0.f, 0.f, 0.f, 0.f);
  float sum = 0.0f;
  for (int p = 0; p < Pp; p++) {
    float a = __expf(s_logit[wslot][p] - mx);
    sum += a;
    int j = (p < 32) ? __shfl_sync(0xffffffffu, idxA, p)
                     : __shfl_sync(0xffffffffu, idxB, p - 32);
    float4 v4 = *(const float4*)(g_qkv + rowbase + (size_t)j * D3 + 2 * D1 + h * EMB + lane * 4);
    acc.x += a * v4.x; acc.y += a * v4.y; acc.z += a * v4.z; acc.w += a * v4.w;
  }
  float inv = 1.0f / sum;
  float4 o = make_float4(acc.x * inv, acc.y * inv, acc.z * inv, acc.w * inv);
  *(float4*)(g_attnout + (size_t)token * D1 + h * EMB + lane * 4) = o;
}

// ---------------- Kernel 4: output GEMM -------------------------------------
// C(4096 x 128) = attnout(4096 x 1024) @ Wu(1024 x 128) + bu
__global__ __launch_bounds__(256) void out_gemm(float* __restrict__ Cout,
                                                const float* __restrict__ Wu,
                                                const float* __restrict__ bu) {
  __shared__ float As[64][68];
  __shared__ float Bs[64][64];
  int bm = blockIdx.y, bn = blockIdx.x;  // bn in {0,1}
  int tid = threadIdx.x;
  int ty = tid >> 4, tx = tid & 15;
  float acc[4][4] = {};
  for (int kc = 0; kc < 1024; kc += 64) {
#pragma unroll
    for (int it = 0; it < 4; it++) {
      int lin = tid + it * 256;
      int r = lin >> 4, c4 = lin & 15;
      float4 v = *(const float4*)(g_attnout + (size_t)(bm * 64 + r) * 1024 + kc + c4 * 4);
      *(float4*)&As[r][c4 * 4] = v;
    }
#pragma unroll
    for (int it = 0; it < 4; it++) {
      int lin = tid + it * 256;
      int k = lin >> 4, c4 = lin & 15;
      float4 v = *(const float4*)(Wu + (size_t)(kc + k) * 128 + bn * 64 + c4 * 4);
      *(float4*)&Bs[k][c4 * 4] = v;
    }
    __syncthreads();
#pragma unroll 8
    for (int k = 0; k < 64; k++) {
      float a0 = As[ty * 4 + 0][k], a1 = As[ty * 4 + 1][k];
      float a2 = As[ty * 4 + 2][k], a3 = As[ty * 4 + 3][k];
      float4 b = *(const float4*)&Bs[k][tx * 4];
      acc[0][0] += a0 * b.x; acc[0][1] += a0 * b.y; acc[0][2] += a0 * b.z; acc[0][3] += a0 * b.w;
      acc[1][0] += a1 * b.x; acc[1][1] += a1 * b.y; acc[1][2] += a1 * b.z; acc[1][3] += a1 * b.w;
      acc[2][0] += a2 * b.x; acc[2][1] += a2 * b.y; acc[2][2] += a2 * b.z; acc[2][3] += a2 * b.w;
      acc[3][0] += a3 * b.x; acc[3][1] += a3 * b.y; acc[3][2] += a3 * b.z; acc[3][3] += a3 * b.w;
    }
    __syncthreads();
  }
  int col0 = bn * 64 + tx * 4;
  float4 bias = *(const float4*)(bu + col0);
#pragma unroll
  for (int i = 0; i < 4; i++) {
    float4 o = make_float4(acc[i][0] + bias.x, acc[i][1] + bias.y,
                           acc[i][2] + bias.z, acc[i][3] + bias.w);
    *(float4*)(Cout + (size_t)(bm * 64 + ty * 4 + i) * 128 + col0) = o;
  }
}

// ---------------- launch ----------------------------------------------------
extern "C" void kernel_launch(void* const* d_in, const int* in_sizes, int n_in,
                              void* d_out, int out_size) {
  const float* x   = (const float*)d_in[0];
  const float* sp  = (const float*)d_in[1];
  const float* mv  = (const float*)d_in[2];
  const float* Wq  = (const float*)d_in[3];
  const float* Wk  = (const float*)d_in[4];
  const float* Wv  = (const float*)d_in[5];
  const float* Wu  = (const float*)d_in[6];
  const float* bu  = (const float*)d_in[7];
  float* out = (float*)d_out;

  qkv_gemm<<<dim3(48, 64), 256>>>(x, Wq, Wk, Wv);
  idxw_kernel<<<BT, 64>>>(sp, mv);
  attn_kernel<<<(BT * NH) / 4, 128>>>();
  out_gemm<<<dim3(2, 64), 256>>>(out, Wu, bu);
}

// round 3
// speedup vs baseline: 1.0451x; 1.0451x over previous
#include <cuda_runtime.h>
#include <stdint.h>
#include <math.h>

// Problem constants
#define Tn    2048
#define EMB   128
#define NH    8
#define Mv    9      // M
#define Pp    36     // P
#define BT    4096   // B*T
#define D1    1024   // NH*EMB
#define D3    3072   // 3*D1

// Scratch (static device arrays; no allocation allowed)
__device__ float g_qkv[BT * D3];      // rows: [Q(1024) | K(1024) | V(1024)]
__device__ float g_attnout[BT * D1];
__device__ int   g_idx[BT * Pp];
__device__ float g_w[BT * Pp];
__device__ float g_part[4][BT * 128]; // split-K partials for out gemm

// ---------------- threefry-2x32 (JAX-compatible, 20 rounds) ----------------
__device__ __forceinline__ void tf2x32(uint32_t k0, uint32_t k1,
                                       uint32_t& x0, uint32_t& x1) {
  uint32_t ks2 = k0 ^ k1 ^ 0x1BD11BDAu;
  x0 += k0; x1 += k1;
#define TFR(r) { x0 += x1; x1 = (x1 << (r)) | (x1 >> (32 - (r))); x1 ^= x0; }
  TFR(13) TFR(15) TFR(26) TFR(6)
  x0 += k1;  x1 += ks2 + 1u;
  TFR(17) TFR(29) TFR(16) TFR(24)
  x0 += ks2; x1 += k0 + 2u;
  TFR(13) TFR(15) TFR(26) TFR(6)
  x0 += k0;  x1 += k1 + 3u;
  TFR(17) TFR(29) TFR(16) TFR(24)
  x0 += k1;  x1 += ks2 + 4u;
  TFR(13) TFR(15) TFR(26) TFR(6)
  x0 += ks2; x1 += k0 + 5u;
#undef TFR
}

// ---------------- Kernel 1: fused QKV projection GEMM ----------------------
// C(4096 x 3072) = X(4096 x 128) @ [Wq | Wk | Wv], Q/K scaled by 1/128^0.25
// 128x64 output tile per 256-thread block, 8x4 per thread, BK=32.
__global__ __launch_bounds__(256) void qkv_gemm(const float* __restrict__ X,
                                                const float* __restrict__ Wq,
                                                const float* __restrict__ Wk,
                                                const float* __restrict__ Wv) {
  __shared__ float As[128][36];  // [m][k] padded
  __shared__ float Bs[32][64];   // [k][n]
  int bm = blockIdx.y, bn = blockIdx.x;
  int cstart = bn * 64;
  int seg = cstart >> 10;
  const float* W = (seg == 0) ? Wq : ((seg == 1) ? Wk : Wv);
  int ccol = cstart & 1023;
  float scale = (seg < 2) ? 0.29730177875068026f : 1.0f; // 1/128^0.25
  int tid = threadIdx.x;
  int ty = tid >> 4, tx = tid & 15;
  float acc[8][4] = {};
  for (int kc = 0; kc < 128; kc += 32) {
    // load X tile 128x32 (rows bm*128.., cols kc..): 1024 float4, 4 iters
#pragma unroll
    for (int it = 0; it < 4; it++) {
      int lin = tid + it * 256;      // 0..1023
      int r = lin >> 3, c4 = lin & 7;
      float4 v = *(const float4*)(X + (size_t)(bm * 128 + r) * 128 + kc + c4 * 4);
      *(float4*)&As[r][c4 * 4] = v;
    }
    // load W tile 32x64 (rows kc.., cols ccol..): 512 float4, 2 iters
#pragma unroll
    for (int it = 0; it < 2; it++) {
      int lin = tid + it * 256;
      int k = lin >> 4, c4 = lin & 15;
      float4 v = *(const float4*)(W + (size_t)(kc + k) * 1024 + ccol + c4 * 4);
      *(float4*)&Bs[k][c4 * 4] = v;
    }
    __syncthreads();
#pragma unroll 8
    for (int k = 0; k < 32; k++) {
      float a[8];
#pragma unroll
      for (int i = 0; i < 8; i++) a[i] = As[ty * 8 + i][k];
      float4 b = *(const float4*)&Bs[k][tx * 4];
#pragma unroll
      for (int i = 0; i < 8; i++) {
        acc[i][0] += a[i] * b.x; acc[i][1] += a[i] * b.y;
        acc[i][2] += a[i] * b.z; acc[i][3] += a[i] * b.w;
      }
    }
    __syncthreads();
  }
#pragma unroll
  for (int i = 0; i < 8; i++) {
    float4 o = make_float4(acc[i][0] * scale, acc[i][1] * scale,
                           acc[i][2] * scale, acc[i][3] * scale);
    *(float4*)(g_qkv + (size_t)(bm * 128 + ty * 8 + i) * D3 + cstart + tx * 4) = o;
  }
}

// ---------------- Kernel 2: indices + weights per token --------------------
__global__ __launch_bounds__(64) void idxw_kernel(const float* __restrict__ sp,
                                                  const float* __restrict__ mvals) {
  int token = blockIdx.x;            // 0..4095
  int b = token >> 11, t = token & 2047;
  int p = threadIdx.x;
  __shared__ float s_mean[Mv];
  __shared__ float s_sigma_inv;
  __shared__ int   s_idx[Pp];
  __shared__ float s_ptsfl[Pp];
  __shared__ float s_dens[Pp][Mv];
  __shared__ float s_colinv[Mv];

  float dil = sp[0];
  if (p < Mv) {
    // exact mul+add (no FMA contraction) to match JAX rounding
    float off = __fmul_rn((float)(p - 4), dil);
    float mu  = __fadd_rn((float)t, off);
    mu = fminf(fmaxf(mu, 0.0f), (float)(Tn - 1));
    s_mean[p] = mu;
  }
  if (p == 0) {
    float s = sp[1] + 2.0f;                 // SIGMA_BOOST
    float sigma = log1pf(expf(s)) + 1e-7f;  // softplus + EPS
    s_sigma_inv = 1.0f / sigma;
  }
  __syncthreads();

  if (p < Pp) {
    int m = p >> 2, slot = p & 3;
    float fl = floorf(s_mean[m]);
    float val;
    if (slot == 0) val = fl;
    else if (slot == 1) val = fl + 1.0f;
    else {
      // JAX partitionable threefry:
      //   split(key(42))[1] = threefry2x32((0,42), (0,1))  [both words]
      //   random_bits elem i: (b1,b2)=threefry2x32(k2,(0,i)); bits=b1^b2
      //   randint span 2048 (pow2) -> bits & 2047
      uint32_t k2a = 0u, k2b = 1u;
      tf2x32(0u, 42u, k2a, k2b);
      uint32_t i = (uint32_t)(b * 36864 + t * 18 + m * 2 + (slot - 2));
      uint32_t x0 = 0u, x1 = i;
      tf2x32(k2a, k2b, x0, x1);
      uint32_t bits = x0 ^ x1;
      val = (float)(bits & 2047u);
    }
    val = fminf(fmaxf(val, 0.0f), (float)(Tn - 1));
    int iv = (int)val;
    s_idx[p] = iv;
    s_ptsfl[p] = (float)iv;
  }
  __syncthreads();

  if (p < Pp) {
    bool dup = false;
    int my = s_idx[p];
    for (int q = 0; q < p; q++) dup |= (s_idx[q] == my);
    float inv_s = s_sigma_inv;
#pragma unroll
    for (int m = 0; m < Mv; m++) {
      float d = (s_ptsfl[p] - s_mean[m]) * inv_s;
      s_dens[p][m] = dup ? 0.0f : expf(-0.5f * d * d);
    }
  }
  __syncthreads();

  if (p < Mv) {
    float sum = 0.0f;
    for (int q = 0; q < Pp; q++) sum += s_dens[q][p];
    s_colinv[p] = 1.0f / sum;
  }
  __syncthreads();

  if (p < Pp) {
    float w = 0.0f;
#pragma unroll
    for (int m = 0; m < Mv; m++) w += s_dens[p][m] * s_colinv[m] * mvals[m];
    g_idx[token * Pp + p] = s_idx[p];
    g_w[token * Pp + p] = w;
  }
}

// ---------------- Kernel 3: gathered attention ------------------------------
// CTA = 16 consecutive tokens x 1 head (16 warps). Adjacent tokens share most
// of their 20 "local" gather rows -> L1 hits instead of L2 traffic.
__global__ __launch_bounds__(512) void attn_kernel() {
  int wid = threadIdx.x >> 5;
  int lane = threadIdx.x & 31;
  __shared__ float s_logit[16][Pp];
  int token = blockIdx.x * 16 + wid;
  int h = blockIdx.y;
  int b = token >> 11;

  float4 q = *(const float4*)(g_qkv + (size_t)token * D3 + h * EMB + lane * 4);

  const int* ip = g_idx + token * Pp;
  const float* wp = g_w + token * Pp;
  int   idxA = ip[lane];
  float wA   = wp[lane];
  int   idxB = (lane < 4) ? ip[32 + lane] : 0;
  float wB   = (lane < 4) ? wp[32 + lane] : 0.0f;

  size_t rowbase = (size_t)(b * Tn) * D3;

  for (int p = 0; p < Pp; p++) {
    int   j = (p < 32) ? __shfl_sync(0xffffffffu, idxA, p)
                       : __shfl_sync(0xffffffffu, idxB, p - 32);
    float w = (p < 32) ? __shfl_sync(0xffffffffu, wA, p)
                       : __shfl_sync(0xffffffffu, wB, p - 32);
    float4 k4 = *(const float4*)(g_qkv + rowbase + (size_t)j * D3 + D1 + h * EMB + lane * 4);
    float d = q.x * k4.x + q.y * k4.y + q.z * k4.z + q.w * k4.w;
    d += __shfl_xor_sync(0xffffffffu, d, 16);
    d += __shfl_xor_sync(0xffffffffu, d, 8);
    d += __shfl_xor_sync(0xffffffffu, d, 4);
    d += __shfl_xor_sync(0xffffffffu, d, 2);
    d += __shfl_xor_sync(0xffffffffu, d, 1);
    if (lane == 0) s_logit[wid][p] = w * d;
  }
  __syncwarp();

  float mx = -1e30f;
#pragma unroll
  for (int p = 0; p < Pp; p++) mx = fmaxf(mx, s_logit[wid][p]);

  float4 acc = make_float4(0.f, 0.f, 0.f, 0.f);
  float sum = 0.0f;
  for (int p = 0; p < Pp; p++) {
    float a = __expf(s_logit[wid][p] - mx);
    sum += a;
    int j = (p < 32) ? __shfl_sync(0xffffffffu, idxA, p)
                     : __shfl_sync(0xffffffffu, idxB, p - 32);
    float4 v4 = *(const float4*)(g_qkv + rowbase + (size_t)j * D3 + 2 * D1 + h * EMB + lane * 4);
    acc.x += a * v4.x; acc.y += a * v4.y; acc.z += a * v4.z; acc.w += a * v4.w;
  }
  float inv = 1.0f / sum;
  float4 o = make_float4(acc.x * inv, acc.y * inv, acc.z * inv, acc.w * inv);
  *(float4*)(g_attnout + (size_t)token * D1 + h * EMB + lane * 4) = o;
}

// ---------------- Kernel 4: output GEMM (split-K x4) -------------------------
// partial[ks](4096 x 128) = attnout(4096 x [ks*256..+256)) @ Wu-slice
__global__ __launch_bounds__(256) void out_gemm_split(const float* __restrict__ Wu) {
  __shared__ float As[64][68];
  __shared__ float Bs[64][64];
  int bm = blockIdx.y, bn = blockIdx.x, ks = blockIdx.z;
  int tid = threadIdx.x;
  int ty = tid >> 4, tx = tid & 15;
  float acc[4][4] = {};
  int kbase = ks * 256;
  for (int kc = kbase; kc < kbase + 256; kc += 64) {
#pragma unroll
    for (int it = 0; it < 4; it++) {
      int lin = tid + it * 256;
      int r = lin >> 4, c4 = lin & 15;
      float4 v = *(const float4*)(g_attnout + (size_t)(bm * 64 + r) * 1024 + kc + c4 * 4);
      *(float4*)&As[r][c4 * 4] = v;
    }
#pragma unroll
    for (int it = 0; it < 4; it++) {
      int lin = tid + it * 256;
      int k = lin >> 4, c4 = lin & 15;
      float4 v = *(const float4*)(Wu + (size_t)(kc + k) * 128 + bn * 64 + c4 * 4);
      *(float4*)&Bs[k][c4 * 4] = v;
    }
    __syncthreads();
#pragma unroll 8
    for (int k = 0; k < 64; k++) {
      float a0 = As[ty * 4 + 0][k], a1 = As[ty * 4 + 1][k];
      float a2 = As[ty * 4 + 2][k], a3 = As[ty * 4 + 3][k];
      float4 b = *(const float4*)&Bs[k][tx * 4];
      acc[0][0] += a0 * b.x; acc[0][1] += a0 * b.y; acc[0][2] += a0 * b.z; acc[0][3] += a0 * b.w;
      acc[1][0] += a1 * b.x; acc[1][1] += a1 * b.y; acc[1][2] += a1 * b.z; acc[1][3] += a1 * b.w;
      acc[2][0] += a2 * b.x; acc[2][1] += a2 * b.y; acc[2][2] += a2 * b.z; acc[2][3] += a2 * b.w;
      acc[3][0] += a3 * b.x; acc[3][1] += a3 * b.y; acc[3][2] += a3 * b.z; acc[3][3] += a3 * b.w;
    }
    __syncthreads();
  }
  int col0 = bn * 64 + tx * 4;
  float* dst = g_part[ks];
#pragma unroll
  for (int i = 0; i < 4; i++) {
    float4 o = make_float4(acc[i][0], acc[i][1], acc[i][2], acc[i][3]);
    *(float4*)(dst + (size_t)(bm * 64 + ty * 4 + i) * 128 + col0) = o;
  }
}

// Deterministic reduce of the 4 split-K partials + bias.
__global__ __launch_bounds__(256) void out_reduce(float* __restrict__ Cout,
                                                  const float* __restrict__ bu) {
  int e4 = blockIdx.x * 256 + threadIdx.x;   // float4 index, 0..131071
  int col0 = (e4 * 4) & 127;
  float4 p0 = *(const float4*)(g_part[0] + e4 * 4);
  float4 p1 = *(const float4*)(g_part[1] + e4 * 4);
  float4 p2 = *(const float4*)(g_part[2] + e4 * 4);
  float4 p3 = *(const float4*)(g_part[3] + e4 * 4);
  float4 bb = *(const float4*)(bu + col0);
  float4 o;
  o.x = ((p0.x + p1.x) + (p2.x + p3.x)) + bb.x;
  o.y = ((p0.y + p1.y) + (p2.y + p3.y)) + bb.y;
  o.z = ((p0.z + p1.z) + (p2.z + p3.z)) + bb.z;
  o.w = ((p0.w + p1.w) + (p2.w + p3.w)) + bb.w;
  *(float4*)(Cout + e4 * 4) = o;
}

// ---------------- launch ----------------------------------------------------
extern "C" void kernel_launch(void* const* d_in, const int* in_sizes, int n_in,
                              void* d_out, int out_size) {
  const float* x   = (const float*)d_in[0];
  const float* sp  = (const float*)d_in[1];
  const float* mv  = (const float*)d_in[2];
  const float* Wq  = (const float*)d_in[3];
  const float* Wk  = (const float*)d_in[4];
  const float* Wv  = (const float*)d_in[5];
  const float* Wu  = (const float*)d_in[6];
  const float* bu  = (const float*)d_in[7];
  float* out = (float*)d_out;

  qkv_gemm<<<dim3(48, 32), 256>>>(x, Wq, Wk, Wv);
  idxw_kernel<<<BT, 64>>>(sp, mv);
  attn_kernel<<<dim3(256, 8), 512>>>();
  out_gemm_split<<<dim3(2, 64, 4), 256>>>(Wu);
  out_reduce<<<512, 256>>>(out, bu);
}